// round 5
// baseline (speedup 1.0000x reference)
#include <cuda_runtime.h>
#include <cuda_bf16.h>
#include <math.h>
#include <stdint.h>

// ---------------------------------------------------------------------------
// FixFeatureAttention sm_103.  R4: spill-free fused attention loop, packed
// bf16x2 polynomial exp, lsum via ones-mma, bf16 tensor-core GEMMs.
// ---------------------------------------------------------------------------

#define HW 4096
#define LOG2E 1.4426950408889634f
#define QSCALE 0.17677669529663687f   // 1/sqrt(32)

__device__ float g_qkv[768 * HW];   // 0..255 Q, 256..511 K, 512..767 V ([chan][pix])
__device__ float g_pos[8 * HW];     // pos bias * LOG2E
__device__ float g_y[256 * HW];     // attention out [o][n]
__device__ float g_proj[512 * HW];

// 64B-row swizzle: XOR bits[5:4] with bits[8:7]
#define SW64R(o) ((o) ^ ((((o) >> 7) & 3) << 4))

__device__ __forceinline__ uint32_t smem_u32(const void* p) {
    uint32_t a;
    asm("{.reg .u64 t; cvta.to.shared.u64 t, %1; cvt.u32.u64 %0, t;}" : "=r"(a) : "l"(p));
    return a;
}
__device__ __forceinline__ uint32_t cvt_bf2(float hi, float lo) {
    uint32_t r;
    asm("cvt.rn.bf16x2.f32 %0, %1, %2;" : "=r"(r) : "f"(hi), "f"(lo));
    return r;
}
__device__ __forceinline__ void ldsm4(uint32_t& r0, uint32_t& r1, uint32_t& r2,
                                      uint32_t& r3, uint32_t a) {
    asm volatile("ldmatrix.sync.aligned.m8n8.x4.shared.b16 {%0,%1,%2,%3}, [%4];"
                 : "=r"(r0), "=r"(r1), "=r"(r2), "=r"(r3) : "r"(a));
}
__device__ __forceinline__ void ldsm4t(uint32_t& r0, uint32_t& r1, uint32_t& r2,
                                       uint32_t& r3, uint32_t a) {
    asm volatile("ldmatrix.sync.aligned.m8n8.x4.trans.shared.b16 {%0,%1,%2,%3}, [%4];"
                 : "=r"(r0), "=r"(r1), "=r"(r2), "=r"(r3) : "r"(a));
}
__device__ __forceinline__ void mma16816(float* c, const uint32_t* a,
                                         uint32_t b0, uint32_t b1) {
    asm volatile(
        "mma.sync.aligned.m16n8k16.row.col.f32.bf16.bf16.f32 "
        "{%0,%1,%2,%3},{%4,%5,%6,%7},{%8,%9},{%0,%1,%2,%3};"
        : "+f"(c[0]), "+f"(c[1]), "+f"(c[2]), "+f"(c[3])
        : "r"(a[0]), "r"(a[1]), "r"(a[2]), "r"(a[3]), "r"(b0), "r"(b1));
}

// packed bf16x2 exp2: x in [-32,32]; magic=192 (ulp=1 in bf16), deg-2 poly.
// Multiplicative poly bias cancels through lsum (same p feeds num & denom).
__device__ __forceinline__ uint32_t pexp2(uint32_t xu, uint32_t posu) {
    uint32_t x, t, u, f, p, q, e, a;
    asm("add.rn.bf16x2 %0, %1, %2;" : "=r"(x) : "r"(xu), "r"(posu));
    asm("add.rn.bf16x2 %0, %1, %2;" : "=r"(t) : "r"(x), "r"(0x43404340u));
    asm("sub.rn.bf16x2 %0, %1, %2;" : "=r"(u) : "r"(t), "r"(0x43404340u));
    asm("sub.rn.bf16x2 %0, %1, %2;" : "=r"(f) : "r"(x), "r"(u));
    asm("fma.rn.bf16x2 %0, %1, %2, %3;" : "=r"(p)
        : "r"(0x3E783E78u), "r"(f), "r"(0x3F343F34u));   // c2*f + c1
    asm("fma.rn.bf16x2 %0, %1, %2, %3;" : "=r"(q)
        : "r"(p), "r"(f), "r"(0x3F803F80u));             // *f + 1
    a = t & 0x007F007Fu;                                  // 7-bit mantissa = 64+i
    e = (a << 7) + 0x1F801F80u;                           // 2^i per half
    asm("mul.rn.bf16x2 %0, %1, %2;" : "=r"(x) : "r"(q), "r"(e));
    return x;
}

// ------------------------- pos bias bilinear 16->64 (xLOG2E) ----------------
__global__ void pos_kernel(const float* __restrict__ pb, float* __restrict__ pos) {
    int i = blockIdx.x * 256 + threadIdx.x;
    if (i >= 8 * HW) return;
    int h = i >> 12, yx = i & 4095;
    int py = yx >> 6, px = yx & 63;
    float sy = (py + 0.5f) * 0.25f - 0.5f;
    float sx = (px + 0.5f) * 0.25f - 0.5f;
    float fy0 = floorf(sy), fx0 = floorf(sx);
    float wy = sy - fy0, wx = sx - fx0;
    int y0 = max((int)fy0, 0), y1 = min((int)fy0 + 1, 15);
    int x0 = max((int)fx0, 0), x1 = min((int)fx0 + 1, 15);
    const float* p = pb + h * 256;
    float v00 = p[y0 * 16 + x0], v01 = p[y0 * 16 + x1];
    float v10 = p[y1 * 16 + x0], v11 = p[y1 * 16 + x1];
    float v0 = v00 + (v01 - v00) * wx;
    float v1 = v10 + (v11 - v10) * wx;
    pos[i] = (v0 + (v1 - v0) * wy) * LOG2E;
}

// ================= bf16 tensor GEMM: C = A[MxK]*B[KxN] (+bias) ==============
// BM=128, BN=128, BK=32, 256 thr, warp = 16 M rows x 128 N.
// A staged [m][k] bf16 64B rows; B staged transposed [n][k]; both SW64R.
__global__ __launch_bounds__(256) void bgemm_kernel(
    const float* __restrict__ A, const float* __restrict__ B,
    const float* __restrict__ bias, float* __restrict__ C,
    int M, int N, int K)
{
    __shared__ __align__(128) char sA[8192];
    __shared__ __align__(128) char sB[8192];
    const int t = threadIdx.x, wid = t >> 5, lane = t & 31;
    const int bm = blockIdx.y * 128, bn = blockIdx.x * 128;
    const uint32_t ab = smem_u32(sA), bb = smem_u32(sB);

    const int ma = t >> 1, qa = t & 1;     // A staging: row, k-half
    const int nb = t & 127, kh = t >> 7;   // B staging: col(n), k-half

    // fragment addresses
    const int fr = wid * 16 + (lane & 7) + ((lane >> 3) & 1) * 8;
    const uint32_t aA0 = ab + SW64R(fr * 64 + (lane >> 4) * 16);
    const uint32_t aA1 = ab + SW64R(fr * 64 + (2 + (lane >> 4)) * 16);
    const int br = (lane & 7) + (lane >> 4) * 8;
    const uint32_t aB0 = bb + SW64R(br * 64 + ((lane >> 3) & 1) * 16);
    const uint32_t aB1 = bb + SW64R(br * 64 + (2 + ((lane >> 3) & 1)) * 16);

    const uint32_t stA0 = ab + SW64R(ma * 64 + qa * 32);
    const uint32_t stA1 = ab + SW64R(ma * 64 + qa * 32 + 16);
    const uint32_t stB0 = bb + SW64R(nb * 64 + kh * 32);
    const uint32_t stB1 = bb + SW64R(nb * 64 + kh * 32 + 16);

    float acc[16][4];
    #pragma unroll
    for (int i = 0; i < 16; i++)
        #pragma unroll
        for (int v = 0; v < 4; v++) acc[i][v] = 0.f;

    const int ntiles = K >> 5;
    float av[16], bv[16];

    // prologue: stage tile 0
    {
        const float* ap = A + (size_t)(bm + ma) * K + qa * 16;
        #pragma unroll
        for (int i = 0; i < 4; i++) {
            float4 x = ((const float4*)ap)[i];
            av[4*i] = x.x; av[4*i+1] = x.y; av[4*i+2] = x.z; av[4*i+3] = x.w;
        }
        const float* bp = B + (size_t)(kh * 16) * HW + bn + nb;
        #pragma unroll
        for (int i = 0; i < 16; i++) bv[i] = bp[(size_t)i * HW];
        uint32_t ua[8], ub[8];
        #pragma unroll
        for (int i = 0; i < 8; i++) {
            ua[i] = cvt_bf2(av[2*i+1], av[2*i]);
            ub[i] = cvt_bf2(bv[2*i+1], bv[2*i]);
        }
        asm volatile("st.shared.v4.b32 [%0], {%1,%2,%3,%4};"
                     :: "r"(stA0), "r"(ua[0]), "r"(ua[1]), "r"(ua[2]), "r"(ua[3]));
        asm volatile("st.shared.v4.b32 [%0], {%1,%2,%3,%4};"
                     :: "r"(stA1), "r"(ua[4]), "r"(ua[5]), "r"(ua[6]), "r"(ua[7]));
        asm volatile("st.shared.v4.b32 [%0], {%1,%2,%3,%4};"
                     :: "r"(stB0), "r"(ub[0]), "r"(ub[1]), "r"(ub[2]), "r"(ub[3]));
        asm volatile("st.shared.v4.b32 [%0], {%1,%2,%3,%4};"
                     :: "r"(stB1), "r"(ub[4]), "r"(ub[5]), "r"(ub[6]), "r"(ub[7]));
    }
    __syncthreads();

    for (int kt = 0; kt < ntiles; kt++) {
        // prefetch next tile into regs
        if (kt + 1 < ntiles) {
            int k0 = (kt + 1) * 32;
            const float* ap = A + (size_t)(bm + ma) * K + k0 + qa * 16;
            #pragma unroll
            for (int i = 0; i < 4; i++) {
                float4 x = ((const float4*)ap)[i];
                av[4*i] = x.x; av[4*i+1] = x.y; av[4*i+2] = x.z; av[4*i+3] = x.w;
            }
            const float* bp = B + (size_t)(k0 + kh * 16) * HW + bn + nb;
            #pragma unroll
            for (int i = 0; i < 16; i++) bv[i] = bp[(size_t)i * HW];
        }

        uint32_t A0[4], A1[4];
        ldsm4(A0[0], A0[1], A0[2], A0[3], aA0);
        ldsm4(A1[0], A1[1], A1[2], A1[3], aA1);
        #pragma unroll
        for (int nch = 0; nch < 8; nch++) {
            uint32_t b00, b01, b02, b03, b10, b11, b12, b13;
            ldsm4(b00, b01, b02, b03, aB0 + nch * 1024);
            ldsm4(b10, b11, b12, b13, aB1 + nch * 1024);
            mma16816(acc[2*nch],   A0, b00, b01);
            mma16816(acc[2*nch],   A1, b10, b11);
            mma16816(acc[2*nch+1], A0, b02, b03);
            mma16816(acc[2*nch+1], A1, b12, b13);
        }
        __syncthreads();
        if (kt + 1 < ntiles) {
            uint32_t ua[8], ub[8];
            #pragma unroll
            for (int i = 0; i < 8; i++) {
                ua[i] = cvt_bf2(av[2*i+1], av[2*i]);
                ub[i] = cvt_bf2(bv[2*i+1], bv[2*i]);
            }
            asm volatile("st.shared.v4.b32 [%0], {%1,%2,%3,%4};"
                         :: "r"(stA0), "r"(ua[0]), "r"(ua[1]), "r"(ua[2]), "r"(ua[3]));
            asm volatile("st.shared.v4.b32 [%0], {%1,%2,%3,%4};"
                         :: "r"(stA1), "r"(ua[4]), "r"(ua[5]), "r"(ua[6]), "r"(ua[7]));
            asm volatile("st.shared.v4.b32 [%0], {%1,%2,%3,%4};"
                         :: "r"(stB0), "r"(ub[0]), "r"(ub[1]), "r"(ub[2]), "r"(ub[3]));
            asm volatile("st.shared.v4.b32 [%0], {%1,%2,%3,%4};"
                         :: "r"(stB1), "r"(ub[4]), "r"(ub[5]), "r"(ub[6]), "r"(ub[7]));
        }
        __syncthreads();
    }

    // epilogue
    int r0 = bm + wid * 16 + (lane >> 2);
    float bv0 = bias ? bias[r0] : 0.f;
    float bv1 = bias ? bias[r0 + 8] : 0.f;
    float* c0p = C + (size_t)r0 * N + bn + (lane & 3) * 2;
    float* c1p = C + (size_t)(r0 + 8) * N + bn + (lane & 3) * 2;
    #pragma unroll
    for (int nc = 0; nc < 16; nc++) {
        float2 w0 = make_float2(acc[nc][0] + bv0, acc[nc][1] + bv0);
        float2 w1 = make_float2(acc[nc][2] + bv1, acc[nc][3] + bv1);
        *(float2*)(c0p + nc * 8) = w0;
        *(float2*)(c1p + nc * 8) = w1;
    }
}

// ===================== mma.sync flash attention (fused) ======================
__global__ __launch_bounds__(256, 2) void attn_kernel(
    const float* __restrict__ qkv, const float* __restrict__ pos,
    float* __restrict__ y)
{
    __shared__ __align__(128) char sQ[8192];
    __shared__ __align__(128) char sK[8192];
    __shared__ __align__(128) char sV[8192];
    __shared__ uint32_t sPosU[64];          // bf16x2 pos pairs

    const int tid  = threadIdx.x;
    const int wid  = tid >> 5;
    const int lane = tid & 31;
    const int g    = lane >> 2;
    const int c    = lane & 3;
    const int h    = blockIdx.y;
    const int q0   = blockIdx.x * 128;

    const float* Qg = qkv + (size_t)(h * 32) * HW;
    const float* Kg = qkv + (size_t)(256 + h * 32) * HW;
    const float* Vg = qkv + (size_t)(512 + h * 32) * HW;
    const float* Pg = pos + (size_t)h * HW;

    const uint32_t qb = smem_u32(sQ), kb = smem_u32(sK), vb = smem_u32(sV);
    const int pix = tid & 127;
    const int d0s = (tid >> 7) * 16;
    const uint32_t st0 = SW64R(pix * 64 + d0s * 2);
    const uint32_t st1 = SW64R(pix * 64 + d0s * 2 + 16);

    // ---- prologue: stage Q (scaled), K/V tile 0, pos tile 0 ----
    {
        float v[16];
        #pragma unroll
        for (int i = 0; i < 16; i++)
            v[i] = Qg[(size_t)(d0s + i) * HW + q0 + pix] * (QSCALE * LOG2E);
        uint32_t b[8];
        #pragma unroll
        for (int i = 0; i < 8; i++) b[i] = cvt_bf2(v[2*i+1], v[2*i]);
        asm volatile("st.shared.v4.b32 [%0], {%1,%2,%3,%4};"
                     :: "r"(qb + st0), "r"(b[0]), "r"(b[1]), "r"(b[2]), "r"(b[3]));
        asm volatile("st.shared.v4.b32 [%0], {%1,%2,%3,%4};"
                     :: "r"(qb + st1), "r"(b[4]), "r"(b[5]), "r"(b[6]), "r"(b[7]));
        float kv[16], vv[16];
        #pragma unroll
        for (int i = 0; i < 16; i++) kv[i] = Kg[(size_t)(d0s + i) * HW + pix];
        #pragma unroll
        for (int i = 0; i < 16; i++) vv[i] = Vg[(size_t)(d0s + i) * HW + pix];
        uint32_t bk[8], bvv[8];
        #pragma unroll
        for (int i = 0; i < 8; i++) {
            bk[i]  = cvt_bf2(kv[2*i+1], kv[2*i]);
            bvv[i] = cvt_bf2(vv[2*i+1], vv[2*i]);
        }
        asm volatile("st.shared.v4.b32 [%0], {%1,%2,%3,%4};"
                     :: "r"(kb + st0), "r"(bk[0]), "r"(bk[1]), "r"(bk[2]), "r"(bk[3]));
        asm volatile("st.shared.v4.b32 [%0], {%1,%2,%3,%4};"
                     :: "r"(kb + st1), "r"(bk[4]), "r"(bk[5]), "r"(bk[6]), "r"(bk[7]));
        asm volatile("st.shared.v4.b32 [%0], {%1,%2,%3,%4};"
                     :: "r"(vb + st0), "r"(bvv[0]), "r"(bvv[1]), "r"(bvv[2]), "r"(bvv[3]));
        asm volatile("st.shared.v4.b32 [%0], {%1,%2,%3,%4};"
                     :: "r"(vb + st1), "r"(bvv[4]), "r"(bvv[5]), "r"(bvv[6]), "r"(bvv[7]));
        if (tid < 64) sPosU[tid] = cvt_bf2(Pg[2*tid+1], Pg[2*tid]);
    }
    __syncthreads();

    // ---- resident Q fragments ----
    uint32_t QA0[4], QA1[4];
    {
        int row = wid * 16 + (lane & 7) + ((lane >> 3) & 1) * 8;
        int ch  = lane >> 4;
        ldsm4(QA0[0], QA0[1], QA0[2], QA0[3], qb + SW64R(row * 64 + ch * 16));
        ldsm4(QA1[0], QA1[1], QA1[2], QA1[3], qb + SW64R(row * 64 + (2 + ch) * 16));
    }
    uint32_t aK0, aK1, aV0, aV1;
    {
        int ko = (lane & 7) + (lane >> 4) * 8;
        int ch = (lane >> 3) & 1;
        aK0 = kb + SW64R(ko * 64 + ch * 16);
        aK1 = kb + SW64R(ko * 64 + (2 + ch) * 16);
    }
    {
        int ko = (lane & 7) + ((lane >> 3) & 1) * 8;
        int ch = lane >> 4;
        aV0 = vb + SW64R(ko * 64 + ch * 16);
        aV1 = vb + SW64R(ko * 64 + (2 + ch) * 16);
    }

    const uint32_t bOne = (lane < 4) ? 0x3F803F80u : 0u;
    float Y[4][4], Ysum[4];
    #pragma unroll
    for (int u = 0; u < 4; u++) {
        Ysum[u] = 0.f;
        #pragma unroll
        for (int v = 0; v < 4; v++) Y[u][v] = 0.f;
    }

    for (int it = 0; it < 32; it++) {
        // prefetch next tile into regs
        float kv[16], vv[16], pa = 0.f, pb2 = 0.f;
        if (it < 31) {
            int j0 = (it + 1) * 128;
            #pragma unroll
            for (int i = 0; i < 16; i++) kv[i] = Kg[(size_t)(d0s + i) * HW + j0 + pix];
            #pragma unroll
            for (int i = 0; i < 16; i++) vv[i] = Vg[(size_t)(d0s + i) * HW + j0 + pix];
            if (tid < 64) { pa = Pg[j0 + 2*tid]; pb2 = Pg[j0 + 2*tid + 1]; }
        }

        // ---- fused S -> exp -> PV over 8 slabs of 16 keys ----
        #pragma unroll
        for (int j = 0; j < 8; j++) {
            uint32_t k00, k01, k02, k03, k10, k11, k12, k13;
            ldsm4(k00, k01, k02, k03, aK0 + j * 1024);
            ldsm4(k10, k11, k12, k13, aK1 + j * 1024);
            float C0[4] = {0.f, 0.f, 0.f, 0.f};
            float C1[4] = {0.f, 0.f, 0.f, 0.f};
            mma16816(C0, QA0, k00, k01);
            mma16816(C0, QA1, k10, k11);
            mma16816(C1, QA0, k02, k03);
            mma16816(C1, QA1, k12, k13);

            uint32_t pos0 = sPosU[j * 8 + c];
            uint32_t pos1 = sPosU[j * 8 + 4 + c];
            uint32_t P[4];
            P[0] = pexp2(cvt_bf2(C0[1], C0[0]), pos0);
            P[1] = pexp2(cvt_bf2(C0[3], C0[2]), pos0);
            P[2] = pexp2(cvt_bf2(C1[1], C1[0]), pos1);
            P[3] = pexp2(cvt_bf2(C1[3], C1[2]), pos1);

            uint32_t v0, v1, v2, v3;
            ldsm4t(v0, v1, v2, v3, aV0 + j * 1024);
            mma16816(Y[0], P, v0, v1);
            mma16816(Y[1], P, v2, v3);
            ldsm4t(v0, v1, v2, v3, aV1 + j * 1024);
            mma16816(Y[2], P, v0, v1);
            mma16816(Y[3], P, v2, v3);
            mma16816(Ysum, P, bOne, bOne);
        }
        __syncthreads();
        if (it < 31) {
            uint32_t bk[8], bvv[8];
            #pragma unroll
            for (int i = 0; i < 8; i++) {
                bk[i]  = cvt_bf2(kv[2*i+1], kv[2*i]);
                bvv[i] = cvt_bf2(vv[2*i+1], vv[2*i]);
            }
            asm volatile("st.shared.v4.b32 [%0], {%1,%2,%3,%4};"
                         :: "r"(kb + st0), "r"(bk[0]), "r"(bk[1]), "r"(bk[2]), "r"(bk[3]));
            asm volatile("st.shared.v4.b32 [%0], {%1,%2,%3,%4};"
                         :: "r"(kb + st1), "r"(bk[4]), "r"(bk[5]), "r"(bk[6]), "r"(bk[7]));
            asm volatile("st.shared.v4.b32 [%0], {%1,%2,%3,%4};"
                         :: "r"(vb + st0), "r"(bvv[0]), "r"(bvv[1]), "r"(bvv[2]), "r"(bvv[3]));
            asm volatile("st.shared.v4.b32 [%0], {%1,%2,%3,%4};"
                         :: "r"(vb + st1), "r"(bvv[4]), "r"(bvv[5]), "r"(bvv[6]), "r"(bvv[7]));
            if (tid < 64) sPosU[tid] = cvt_bf2(pb2, pa);
        }
        __syncthreads();
    }

    // lsum lives in Ysum[0]/Ysum[2] on lanes with c==0; broadcast in quad
    float lsA = __shfl_sync(0xffffffffu, Ysum[0], lane & 28);
    float lsB = __shfl_sync(0xffffffffu, Ysum[2], lane & 28);
    float invA = 1.f / lsA, invB = 1.f / lsB;

    int row = q0 + wid * 16 + g;
    #pragma unroll
    for (int v = 0; v < 4; v++) {
        int d = h * 32 + v * 8 + 2 * c;
        y[(size_t)d * HW + row]           = Y[v][0] * invA;
        y[(size_t)(d + 1) * HW + row]     = Y[v][1] * invA;
        y[(size_t)d * HW + row + 8]       = Y[v][2] * invB;
        y[(size_t)(d + 1) * HW + row + 8] = Y[v][3] * invB;
    }
}

// --------------------- residual + channel LayerNorm -------------------------
__global__ __launch_bounds__(256) void ln_kernel(
    const float* __restrict__ x, const float* __restrict__ yp,
    const float* __restrict__ gamma, const float* __restrict__ beta,
    float* __restrict__ out)
{
    __shared__ float ssum[8][32], ssq[8][32];
    int nx = threadIdx.x & 31;
    int cg = threadIdx.x >> 5;
    int n  = blockIdx.x * 32 + nx;
    float sum = 0.f, sq = 0.f;
    for (int c = cg; c < 512; c += 8) {
        float z = x[(size_t)c * HW + n] + yp[(size_t)c * HW + n];
        sum += z; sq += z * z;
    }
    ssum[cg][nx] = sum; ssq[cg][nx] = sq;
    __syncthreads();
    float tot = 0.f, totsq = 0.f;
    #pragma unroll
    for (int g = 0; g < 8; g++) { tot += ssum[g][nx]; totsq += ssq[g][nx]; }
    float mu   = tot * (1.f / 512.f);
    float var  = totsq * (1.f / 512.f) - mu * mu;
    float rstd = rsqrtf(var + 1e-5f);
    for (int c = cg; c < 512; c += 8) {
        float z = x[(size_t)c * HW + n] + yp[(size_t)c * HW + n];
        out[(size_t)c * HW + n] = (z - mu) * rstd * gamma[c] + beta[c];
    }
}

// -----------------------------------------------------------------------------
extern "C" void kernel_launch(void* const* d_in, const int* in_sizes, int n_in,
                              void* d_out, int out_size) {
    const float* x        = (const float*)d_in[0];
    const float* w_qkv    = (const float*)d_in[1];
    const float* w_proj   = (const float*)d_in[2];
    const float* b_proj   = (const float*)d_in[3];
    const float* pos_bias = (const float*)d_in[4];
    const float* gamma    = (const float*)d_in[5];
    const float* beta     = (const float*)d_in[6];
    float* out = (float*)d_out;

    float *qkv, *pos, *y, *proj;
    cudaGetSymbolAddress((void**)&qkv,  g_qkv);
    cudaGetSymbolAddress((void**)&pos,  g_pos);
    cudaGetSymbolAddress((void**)&y,    g_y);
    cudaGetSymbolAddress((void**)&proj, g_proj);

    pos_kernel<<<128, 256>>>(pos_bias, pos);
    bgemm_kernel<<<dim3(32, 6), 256>>>(w_qkv, x, nullptr, qkv, 768, HW, 512);
    attn_kernel<<<dim3(32, 8), 256>>>(qkv, pos, y);
    bgemm_kernel<<<dim3(32, 4), 256>>>(w_proj, y, b_proj, proj, 512, HW, 256);
    ln_kernel<<<128, 256>>>(x, proj, gamma, beta, out);
}

// round 6
// speedup vs baseline: 1.0492x; 1.0492x over previous
#include <cuda_runtime.h>
#include <cuda_bf16.h>
#include <math.h>
#include <stdint.h>

// ---------------------------------------------------------------------------
// FixFeatureAttention sm_103.  R6: pre-packed bf16 swizzled QKV tiles in gmem,
// cp.async double-buffered attention, packed bf16x2 exp, ones-mma lsum,
// register-cached LayerNorm.
// ---------------------------------------------------------------------------

#define HW 4096
#define LOG2E 1.4426950408889634f
#define QSCALE 0.17677669529663687f   // 1/sqrt(32)

__device__ float    g_qkv[768 * HW];       // fp32 qkv [chan][pix]
__device__ float    g_y[256 * HW];         // attention out [o][n]
__device__ float    g_proj[512 * HW];
__device__ uint8_t  g_tiles[6 * 1024 * 1024];  // bf16 swizzled tiles: (type*8+h)*32+j, 8KB each
__device__ uint32_t g_posb[8 * 2048];      // pos*LOG2E as bf16x2 pairs

// 64B-row swizzle: XOR bits[5:4] with bits[8:7]
#define SW64R(o) ((o) ^ ((((o) >> 7) & 3) << 4))

__device__ __forceinline__ uint32_t smem_u32(const void* p) {
    uint32_t a;
    asm("{.reg .u64 t; cvta.to.shared.u64 t, %1; cvt.u32.u64 %0, t;}" : "=r"(a) : "l"(p));
    return a;
}
__device__ __forceinline__ uint32_t cvt_bf2(float hi, float lo) {
    uint32_t r;
    asm("cvt.rn.bf16x2.f32 %0, %1, %2;" : "=r"(r) : "f"(hi), "f"(lo));
    return r;
}
__device__ __forceinline__ void ldsm4(uint32_t& r0, uint32_t& r1, uint32_t& r2,
                                      uint32_t& r3, uint32_t a) {
    asm volatile("ldmatrix.sync.aligned.m8n8.x4.shared.b16 {%0,%1,%2,%3}, [%4];"
                 : "=r"(r0), "=r"(r1), "=r"(r2), "=r"(r3) : "r"(a));
}
__device__ __forceinline__ void ldsm4t(uint32_t& r0, uint32_t& r1, uint32_t& r2,
                                       uint32_t& r3, uint32_t a) {
    asm volatile("ldmatrix.sync.aligned.m8n8.x4.trans.shared.b16 {%0,%1,%2,%3}, [%4];"
                 : "=r"(r0), "=r"(r1), "=r"(r2), "=r"(r3) : "r"(a));
}
__device__ __forceinline__ void mma16816(float* c, const uint32_t* a,
                                         uint32_t b0, uint32_t b1) {
    asm volatile(
        "mma.sync.aligned.m16n8k16.row.col.f32.bf16.bf16.f32 "
        "{%0,%1,%2,%3},{%4,%5,%6,%7},{%8,%9},{%0,%1,%2,%3};"
        : "+f"(c[0]), "+f"(c[1]), "+f"(c[2]), "+f"(c[3])
        : "r"(a[0]), "r"(a[1]), "r"(a[2]), "r"(a[3]), "r"(b0), "r"(b1));
}
#define CP16(dst, src) asm volatile("cp.async.cg.shared.global [%0], [%1], 16;" \
                                    :: "r"(dst), "l"(src) : "memory")
#define CPCOMMIT()     asm volatile("cp.async.commit_group;" ::: "memory")
#define CPWAIT0()      asm volatile("cp.async.wait_group 0;" ::: "memory")

// packed bf16x2 exp2: magic=192 range reduce, deg-2 poly (bias cancels via lsum)
__device__ __forceinline__ uint32_t pexp2(uint32_t xu, uint32_t posu) {
    uint32_t x, t, u, f, p, q, e, a;
    asm("add.rn.bf16x2 %0, %1, %2;" : "=r"(x) : "r"(xu), "r"(posu));
    asm("add.rn.bf16x2 %0, %1, %2;" : "=r"(t) : "r"(x), "r"(0x43404340u));
    asm("sub.rn.bf16x2 %0, %1, %2;" : "=r"(u) : "r"(t), "r"(0x43404340u));
    asm("sub.rn.bf16x2 %0, %1, %2;" : "=r"(f) : "r"(x), "r"(u));
    asm("fma.rn.bf16x2 %0, %1, %2, %3;" : "=r"(p)
        : "r"(0x3E783E78u), "r"(f), "r"(0x3F343F34u));
    asm("fma.rn.bf16x2 %0, %1, %2, %3;" : "=r"(q)
        : "r"(p), "r"(f), "r"(0x3F803F80u));
    a = t & 0x007F007Fu;
    e = (a << 7) + 0x1F801F80u;
    asm("mul.rn.bf16x2 %0, %1, %2;" : "=r"(x) : "r"(q), "r"(e));
    return x;
}

// ----------------- pos bias bilinear 16->64, packed bf16x2 (xLOG2E) ---------
__global__ void pos_kernel(const float* __restrict__ pb, uint32_t* __restrict__ posb) {
    int i = blockIdx.x * 256 + threadIdx.x;     // pair index
    if (i >= 8 * 2048) return;
    int h = i >> 11, jp = i & 2047;
    float v[2];
    #pragma unroll
    for (int s = 0; s < 2; s++) {
        int j = jp * 2 + s;
        int py = j >> 6, px = j & 63;
        float sy = (py + 0.5f) * 0.25f - 0.5f;
        float sx = (px + 0.5f) * 0.25f - 0.5f;
        float fy0 = floorf(sy), fx0 = floorf(sx);
        float wy = sy - fy0, wx = sx - fx0;
        int y0 = max((int)fy0, 0), y1 = min((int)fy0 + 1, 15);
        int x0 = max((int)fx0, 0), x1 = min((int)fx0 + 1, 15);
        const float* p = pb + h * 256;
        float v00 = p[y0 * 16 + x0], v01 = p[y0 * 16 + x1];
        float v10 = p[y1 * 16 + x0], v11 = p[y1 * 16 + x1];
        float va = v00 + (v01 - v00) * wx;
        float vb = v10 + (v11 - v10) * wx;
        v[s] = (va + (vb - va) * wy) * LOG2E;
    }
    posb[i] = cvt_bf2(v[1], v[0]);
}

// ================= bf16 tensor GEMM: C = A[MxK]*B[KxN] (+bias) ==============
__global__ __launch_bounds__(256) void bgemm_kernel(
    const float* __restrict__ A, const float* __restrict__ B,
    const float* __restrict__ bias, float* __restrict__ C,
    int M, int N, int K)
{
    __shared__ __align__(128) char sA[8192];
    __shared__ __align__(128) char sB[8192];
    const int t = threadIdx.x, wid = t >> 5, lane = t & 31;
    const int bm = blockIdx.y * 128, bn = blockIdx.x * 128;
    const uint32_t ab = smem_u32(sA), bb = smem_u32(sB);

    const int ma = t >> 1, qa = t & 1;
    const int nb = t & 127, kh = t >> 7;

    const int fr = wid * 16 + (lane & 7) + ((lane >> 3) & 1) * 8;
    const uint32_t aA0 = ab + SW64R(fr * 64 + (lane >> 4) * 16);
    const uint32_t aA1 = ab + SW64R(fr * 64 + (2 + (lane >> 4)) * 16);
    const int br = (lane & 7) + (lane >> 4) * 8;
    const uint32_t aB0 = bb + SW64R(br * 64 + ((lane >> 3) & 1) * 16);
    const uint32_t aB1 = bb + SW64R(br * 64 + (2 + ((lane >> 3) & 1)) * 16);

    const uint32_t stA0 = ab + SW64R(ma * 64 + qa * 32);
    const uint32_t stA1 = ab + SW64R(ma * 64 + qa * 32 + 16);
    const uint32_t stB0 = bb + SW64R(nb * 64 + kh * 32);
    const uint32_t stB1 = bb + SW64R(nb * 64 + kh * 32 + 16);

    float acc[16][4];
    #pragma unroll
    for (int i = 0; i < 16; i++)
        #pragma unroll
        for (int v = 0; v < 4; v++) acc[i][v] = 0.f;

    const int ntiles = K >> 5;
    float av[16], bv[16];

    {
        const float* ap = A + (size_t)(bm + ma) * K + qa * 16;
        #pragma unroll
        for (int i = 0; i < 4; i++) {
            float4 x = ((const float4*)ap)[i];
            av[4*i] = x.x; av[4*i+1] = x.y; av[4*i+2] = x.z; av[4*i+3] = x.w;
        }
        const float* bp = B + (size_t)(kh * 16) * HW + bn + nb;
        #pragma unroll
        for (int i = 0; i < 16; i++) bv[i] = bp[(size_t)i * HW];
        uint32_t ua[8], ub[8];
        #pragma unroll
        for (int i = 0; i < 8; i++) {
            ua[i] = cvt_bf2(av[2*i+1], av[2*i]);
            ub[i] = cvt_bf2(bv[2*i+1], bv[2*i]);
        }
        asm volatile("st.shared.v4.b32 [%0], {%1,%2,%3,%4};"
                     :: "r"(stA0), "r"(ua[0]), "r"(ua[1]), "r"(ua[2]), "r"(ua[3]));
        asm volatile("st.shared.v4.b32 [%0], {%1,%2,%3,%4};"
                     :: "r"(stA1), "r"(ua[4]), "r"(ua[5]), "r"(ua[6]), "r"(ua[7]));
        asm volatile("st.shared.v4.b32 [%0], {%1,%2,%3,%4};"
                     :: "r"(stB0), "r"(ub[0]), "r"(ub[1]), "r"(ub[2]), "r"(ub[3]));
        asm volatile("st.shared.v4.b32 [%0], {%1,%2,%3,%4};"
                     :: "r"(stB1), "r"(ub[4]), "r"(ub[5]), "r"(ub[6]), "r"(ub[7]));
    }
    __syncthreads();

    for (int kt = 0; kt < ntiles; kt++) {
        if (kt + 1 < ntiles) {
            int k0 = (kt + 1) * 32;
            const float* ap = A + (size_t)(bm + ma) * K + k0 + qa * 16;
            #pragma unroll
            for (int i = 0; i < 4; i++) {
                float4 x = ((const float4*)ap)[i];
                av[4*i] = x.x; av[4*i+1] = x.y; av[4*i+2] = x.z; av[4*i+3] = x.w;
            }
            const float* bp = B + (size_t)(k0 + kh * 16) * HW + bn + nb;
            #pragma unroll
            for (int i = 0; i < 16; i++) bv[i] = bp[(size_t)i * HW];
        }

        uint32_t A0[4], A1[4];
        ldsm4(A0[0], A0[1], A0[2], A0[3], aA0);
        ldsm4(A1[0], A1[1], A1[2], A1[3], aA1);
        #pragma unroll
        for (int nch = 0; nch < 8; nch++) {
            uint32_t b00, b01, b02, b03, b10, b11, b12, b13;
            ldsm4(b00, b01, b02, b03, aB0 + nch * 1024);
            ldsm4(b10, b11, b12, b13, aB1 + nch * 1024);
            mma16816(acc[2*nch],   A0, b00, b01);
            mma16816(acc[2*nch],   A1, b10, b11);
            mma16816(acc[2*nch+1], A0, b02, b03);
            mma16816(acc[2*nch+1], A1, b12, b13);
        }
        __syncthreads();
        if (kt + 1 < ntiles) {
            uint32_t ua[8], ub[8];
            #pragma unroll
            for (int i = 0; i < 8; i++) {
                ua[i] = cvt_bf2(av[2*i+1], av[2*i]);
                ub[i] = cvt_bf2(bv[2*i+1], bv[2*i]);
            }
            asm volatile("st.shared.v4.b32 [%0], {%1,%2,%3,%4};"
                         :: "r"(stA0), "r"(ua[0]), "r"(ua[1]), "r"(ua[2]), "r"(ua[3]));
            asm volatile("st.shared.v4.b32 [%0], {%1,%2,%3,%4};"
                         :: "r"(stA1), "r"(ua[4]), "r"(ua[5]), "r"(ua[6]), "r"(ua[7]));
            asm volatile("st.shared.v4.b32 [%0], {%1,%2,%3,%4};"
                         :: "r"(stB0), "r"(ub[0]), "r"(ub[1]), "r"(ub[2]), "r"(ub[3]));
            asm volatile("st.shared.v4.b32 [%0], {%1,%2,%3,%4};"
                         :: "r"(stB1), "r"(ub[4]), "r"(ub[5]), "r"(ub[6]), "r"(ub[7]));
        }
        __syncthreads();
    }

    int r0 = bm + wid * 16 + (lane >> 2);
    float bv0 = bias ? bias[r0] : 0.f;
    float bv1 = bias ? bias[r0 + 8] : 0.f;
    float* c0p = C + (size_t)r0 * N + bn + (lane & 3) * 2;
    float* c1p = C + (size_t)(r0 + 8) * N + bn + (lane & 3) * 2;
    #pragma unroll
    for (int nc = 0; nc < 16; nc++) {
        *(float2*)(c0p + nc * 8) = make_float2(acc[nc][0] + bv0, acc[nc][1] + bv0);
        *(float2*)(c1p + nc * 8) = make_float2(acc[nc][2] + bv1, acc[nc][3] + bv1);
    }
}

// ------------- pack qkv fp32 -> bf16 swizzled 8KB tiles in gmem -------------
// grid (32 tiles, 8 heads, 3 types), 256 thr. Q gets QSCALE*LOG2E folded in.
__global__ __launch_bounds__(256) void pack_kernel(
    const float* __restrict__ qkv, uint8_t* __restrict__ tiles)
{
    const int jb = blockIdx.x, h = blockIdx.y, type = blockIdx.z;
    const int tid = threadIdx.x;
    const int pix = tid & 127, d0s = (tid >> 7) * 16;
    const float scale = (type == 0) ? (QSCALE * LOG2E) : 1.0f;
    const float* src = qkv + (size_t)(type * 256 + h * 32 + d0s) * HW + jb * 128 + pix;
    float v[16];
    #pragma unroll
    for (int i = 0; i < 16; i++) v[i] = src[(size_t)i * HW] * scale;
    uint32_t b[8];
    #pragma unroll
    for (int i = 0; i < 8; i++) b[i] = cvt_bf2(v[2*i+1], v[2*i]);
    uint8_t* blob = tiles + (size_t)((type * 8 + h) * 32 + jb) * 8192;
    *(uint4*)(blob + SW64R(pix * 64 + d0s * 2))      = make_uint4(b[0], b[1], b[2], b[3]);
    *(uint4*)(blob + SW64R(pix * 64 + d0s * 2 + 16)) = make_uint4(b[4], b[5], b[6], b[7]);
}

// ===================== flash attention (cp.async, double-buffered) ==========
__global__ __launch_bounds__(256, 2) void attn_kernel(
    const uint8_t* __restrict__ tiles, const uint32_t* __restrict__ posb,
    float* __restrict__ y)
{
    __shared__ __align__(128) char sQ[8192];
    __shared__ __align__(128) char sK[16384];   // 2 buffers
    __shared__ __align__(128) char sV[16384];   // 2 buffers
    __shared__ __align__(16)  char sPos[512];   // 2 buffers of 256B

    const int tid  = threadIdx.x;
    const int wid  = tid >> 5;
    const int lane = tid & 31;
    const int g    = lane >> 2;
    const int c    = lane & 3;
    const int h    = blockIdx.y;
    const int q0   = blockIdx.x * 128;

    const uint32_t qb = smem_u32(sQ), kb = smem_u32(sK), vb = smem_u32(sV);
    const uint32_t pbs = smem_u32(sPos);

    const uint8_t* tQ = tiles + (size_t)(h * 32 + blockIdx.x) * 8192;
    const uint8_t* tK = tiles + (size_t)((8 + h) * 32) * 8192;
    const uint8_t* tV = tiles + (size_t)((16 + h) * 32) * 8192;
    const uint8_t* tP = (const uint8_t*)(posb + h * 2048);

    // ---- prologue: Q + K0/V0 + pos0 via cp.async ----
    {
        uint32_t o = tid << 4;
        CP16(qb + o,        tQ + o);
        CP16(qb + o + 4096, tQ + o + 4096);
        CP16(kb + o,        tK + o);
        CP16(kb + o + 4096, tK + o + 4096);
        CP16(vb + o,        tV + o);
        CP16(vb + o + 4096, tV + o + 4096);
        if (tid < 16) CP16(pbs + (tid << 4), tP + (tid << 4));
        CPCOMMIT();
        CPWAIT0();
    }
    __syncthreads();

    // ---- resident Q fragments + ldsm bases ----
    uint32_t QA0[4], QA1[4];
    {
        int row = wid * 16 + (lane & 7) + ((lane >> 3) & 1) * 8;
        int ch  = lane >> 4;
        ldsm4(QA0[0], QA0[1], QA0[2], QA0[3], qb + SW64R(row * 64 + ch * 16));
        ldsm4(QA1[0], QA1[1], QA1[2], QA1[3], qb + SW64R(row * 64 + (2 + ch) * 16));
    }
    uint32_t aK0, aK1, aV0, aV1;
    {
        int ko = (lane & 7) + (lane >> 4) * 8;
        int ch = (lane >> 3) & 1;
        aK0 = kb + SW64R(ko * 64 + ch * 16);
        aK1 = kb + SW64R(ko * 64 + (2 + ch) * 16);
    }
    {
        int ko = (lane & 7) + ((lane >> 3) & 1) * 8;
        int ch = lane >> 4;
        aV0 = vb + SW64R(ko * 64 + ch * 16);
        aV1 = vb + SW64R(ko * 64 + (2 + ch) * 16);
    }

    const uint32_t bOne = (lane < 4) ? 0x3F803F80u : 0u;
    float Y[4][4], Ysum[4];
    #pragma unroll
    for (int u = 0; u < 4; u++) {
        Ysum[u] = 0.f;
        #pragma unroll
        for (int v = 0; v < 4; v++) Y[u][v] = 0.f;
    }

    for (int it = 0; it < 32; it++) {
        const uint32_t bofs = (uint32_t)(it & 1) * 8192;

        if (it < 31) {
            const uint32_t nofs = (uint32_t)((it + 1) & 1) * 8192;
            const size_t jo = (size_t)(it + 1) * 8192;
            uint32_t o = tid << 4;
            CP16(kb + nofs + o,        tK + jo + o);
            CP16(kb + nofs + o + 4096, tK + jo + o + 4096);
            CP16(vb + nofs + o,        tV + jo + o);
            CP16(vb + nofs + o + 4096, tV + jo + o + 4096);
            if (tid < 16)
                CP16(pbs + (((it + 1) & 1) << 8) + (tid << 4),
                     tP + (size_t)(it + 1) * 256 + (tid << 4));
            CPCOMMIT();
        }

        const uint32_t kA0 = aK0 + bofs, kA1 = aK1 + bofs;
        const uint32_t vA0 = aV0 + bofs, vA1 = aV1 + bofs;
        const uint32_t* sp = (const uint32_t*)(sPos + (it & 1) * 256);

        #pragma unroll
        for (int j = 0; j < 8; j++) {
            uint32_t k00, k01, k02, k03, k10, k11, k12, k13;
            ldsm4(k00, k01, k02, k03, kA0 + j * 1024);
            ldsm4(k10, k11, k12, k13, kA1 + j * 1024);
            float C0[4] = {0.f, 0.f, 0.f, 0.f};
            float C1[4] = {0.f, 0.f, 0.f, 0.f};
            mma16816(C0, QA0, k00, k01);
            mma16816(C0, QA1, k10, k11);
            mma16816(C1, QA0, k02, k03);
            mma16816(C1, QA1, k12, k13);

            uint32_t pos0 = sp[j * 8 + c];
            uint32_t pos1 = sp[j * 8 + 4 + c];
            uint32_t P[4];
            P[0] = pexp2(cvt_bf2(C0[1], C0[0]), pos0);
            P[1] = pexp2(cvt_bf2(C0[3], C0[2]), pos0);
            P[2] = pexp2(cvt_bf2(C1[1], C1[0]), pos1);
            P[3] = pexp2(cvt_bf2(C1[3], C1[2]), pos1);

            uint32_t v0, v1, v2, v3;
            ldsm4t(v0, v1, v2, v3, vA0 + j * 1024);
            mma16816(Y[0], P, v0, v1);
            mma16816(Y[1], P, v2, v3);
            ldsm4t(v0, v1, v2, v3, vA1 + j * 1024);
            mma16816(Y[2], P, v0, v1);
            mma16816(Y[3], P, v2, v3);
            mma16816(Ysum, P, bOne, bOne);
        }

        if (it < 31) CPWAIT0();
        __syncthreads();
    }

    float lsA = __shfl_sync(0xffffffffu, Ysum[0], lane & 28);
    float lsB = __shfl_sync(0xffffffffu, Ysum[2], lane & 28);
    float invA = 1.f / lsA, invB = 1.f / lsB;

    int row = q0 + wid * 16 + g;
    #pragma unroll
    for (int v = 0; v < 4; v++) {
        int d = h * 32 + v * 8 + 2 * c;
        y[(size_t)d * HW + row]           = Y[v][0] * invA;
        y[(size_t)(d + 1) * HW + row]     = Y[v][1] * invA;
        y[(size_t)d * HW + row + 8]       = Y[v][2] * invB;
        y[(size_t)(d + 1) * HW + row + 8] = Y[v][3] * invB;
    }
}

// --------------- residual + channel LayerNorm (z cached in regs) ------------
__global__ __launch_bounds__(256) void ln_kernel(
    const float* __restrict__ x, const float* __restrict__ yp,
    const float* __restrict__ gamma, const float* __restrict__ beta,
    float* __restrict__ out)
{
    __shared__ float ssum[8][32], ssq[8][32];
    int nx = threadIdx.x & 31;
    int cg = threadIdx.x >> 5;
    int n  = blockIdx.x * 32 + nx;

    float z[64];
    float sum = 0.f, sq = 0.f;
    #pragma unroll
    for (int i = 0; i < 64; i++) {
        int c = cg + i * 8;
        z[i] = x[(size_t)c * HW + n] + yp[(size_t)c * HW + n];
        sum += z[i]; sq += z[i] * z[i];
    }
    ssum[cg][nx] = sum; ssq[cg][nx] = sq;
    __syncthreads();
    float tot = 0.f, totsq = 0.f;
    #pragma unroll
    for (int g = 0; g < 8; g++) { tot += ssum[g][nx]; totsq += ssq[g][nx]; }
    float mu   = tot * (1.f / 512.f);
    float var  = totsq * (1.f / 512.f) - mu * mu;
    float rstd = rsqrtf(var + 1e-5f);
    #pragma unroll
    for (int i = 0; i < 64; i++) {
        int c = cg + i * 8;
        out[(size_t)c * HW + n] = (z[i] - mu) * rstd * gamma[c] + beta[c];
    }
}

// -----------------------------------------------------------------------------
extern "C" void kernel_launch(void* const* d_in, const int* in_sizes, int n_in,
                              void* d_out, int out_size) {
    const float* x        = (const float*)d_in[0];
    const float* w_qkv    = (const float*)d_in[1];
    const float* w_proj   = (const float*)d_in[2];
    const float* b_proj   = (const float*)d_in[3];
    const float* pos_bias = (const float*)d_in[4];
    const float* gamma    = (const float*)d_in[5];
    const float* beta     = (const float*)d_in[6];
    float* out = (float*)d_out;

    float *qkv, *yb, *proj;
    uint8_t* tiles;
    uint32_t* posb;
    cudaGetSymbolAddress((void**)&qkv,   g_qkv);
    cudaGetSymbolAddress((void**)&yb,    g_y);
    cudaGetSymbolAddress((void**)&proj,  g_proj);
    cudaGetSymbolAddress((void**)&tiles, g_tiles);
    cudaGetSymbolAddress((void**)&posb,  g_posb);

    pos_kernel<<<64, 256>>>(pos_bias, posb);
    bgemm_kernel<<<dim3(32, 6), 256>>>(w_qkv, x, nullptr, qkv, 768, HW, 512);
    pack_kernel<<<dim3(32, 8, 3), 256>>>(qkv, tiles);
    attn_kernel<<<dim3(32, 8), 256>>>(tiles, posb, yb);
    bgemm_kernel<<<dim3(32, 4), 256>>>(w_proj, yb, b_proj, proj, 512, HW, 256);
    ln_kernel<<<128, 256>>>(x, proj, gamma, beta, out);
}